// round 15
// baseline (speedup 1.0000x reference)
#include <cuda_runtime.h>
#include <cstdint>

#define N_NODES 50000
#define N_EDGES 800000
#define HID     128
#define N_GRAPHS 32
#define LN_EPS  1e-5f
#define NBLK    196                         // ceil(50000/256)
#define EBLK2   1563                        // ceil(800000/2/256)
#define WPBLK   80                          // ceil(5*128*32/256)
#define MMA_BLOCKS ((N_NODES + 127) / 128)  // 391
#define SKW 68                              // smem row stride in u32 (272B)

typedef unsigned int u32;

// ---------------- scratch (device globals; zero-initialized at load) ----------------
__device__ float g_h[N_NODES * HID];
__device__ __align__(16) u32 g_tb[N_NODES * HID / 2];   // t' as bf16x2
__device__ __align__(16) u32 g_Whi[5 * HID * HID / 2];  // W bf16 hi, [o][k] pairs
__device__ __align__(16) u32 g_Wlo[5 * HID * HID / 2];  // W bf16 lo
__device__ float g_dis[N_NODES];
__device__ int   g_edeg[N_NODES];           // ZEROED at end of every launch (and at load)
__device__ int   g_edeg2[N_NODES];          // second counter bank (halves atomic contention)
__device__ int   g_off[N_NODES + 1];
__device__ int   g_cursor[N_NODES];
__device__ int   g_csr[N_EDGES];
__device__ int   g_row[N_EDGES];
__device__ int   g_col[N_EDGES];
__device__ int   g_batch[N_NODES];
__device__ int   g_bsum[NBLK];
__device__ int   g_scan_cnt;                // ZEROED at end of every launch
__device__ float g_sums[N_GRAPHS];          // ZEROED at end of every launch
__device__ int   g_cnts[N_GRAPHS];          // ZEROED at end of every launch

// ---------------- helpers ----------------
__device__ __forceinline__ u32 cvt2(float hi_elem, float lo_elem) {
    u32 r; asm("cvt.rn.bf16x2.f32 %0, %1, %2;" : "=r"(r) : "f"(hi_elem), "f"(lo_elem)); return r;
}
__device__ __forceinline__ float bf_lo(u32 v) { return __uint_as_float(v << 16); }
__device__ __forceinline__ float bf_hi(u32 v) { return __uint_as_float(v & 0xffff0000u); }

__device__ __forceinline__ u32 smem_u32(const void* p) {
    u32 a;
    asm("{ .reg .u64 t; cvta.to.shared.u64 t, %1; cvt.u32.u64 %0, t; }" : "=r"(a) : "l"(p));
    return a;
}
__device__ __forceinline__ void ldm4(u32& r0, u32& r1, u32& r2, u32& r3, u32 addr) {
    asm volatile("ldmatrix.sync.aligned.m8n8.x4.shared.b16 {%0,%1,%2,%3}, [%4];"
                 : "=r"(r0), "=r"(r1), "=r"(r2), "=r"(r3) : "r"(addr));
}
__device__ __forceinline__ void mma16816(float& c0, float& c1, float& c2, float& c3,
                                         u32 a0, u32 a1, u32 a2, u32 a3, u32 b0, u32 b1) {
    asm volatile(
        "mma.sync.aligned.m16n8k16.row.col.f32.bf16.bf16.f32 "
        "{%0,%1,%2,%3}, {%4,%5,%6,%7}, {%8,%9}, {%0,%1,%2,%3};"
        : "+f"(c0), "+f"(c1), "+f"(c2), "+f"(c3)
        : "r"(a0), "r"(a1), "r"(a2), "r"(a3), "r"(b0), "r"(b1));
}
__device__ __forceinline__ void add4(float& a0, float& a1, float& a2, float& a3, uint2 m) {
    a0 += bf_lo(m.x); a1 += bf_hi(m.x); a2 += bf_lo(m.y); a3 += bf_hi(m.y);
}
__device__ __forceinline__ int detect64(const unsigned int* w) {
    __shared__ int sflag;
    if (threadIdx.x < 32) {
        unsigned ok = 1;
        #pragma unroll
        for (int j = 0; j < 4; j++) ok &= (w[1 + 2 * (threadIdx.x * 4 + j)] == 0u);
        unsigned all = __ballot_sync(0xffffffffu, ok != 0);
        if (threadIdx.x == 0) sflag = (all == 0xffffffffu);
    }
    __syncthreads();
    return sflag;
}

// ---- critical path: col conversion + degree atomics (2 edges/thread, split banks) ----
__global__ void __launch_bounds__(256) k_deg(const void* ei) {
    int f64 = detect64((const unsigned int*)ei);
    int idx = blockIdx.x * 256 + threadIdx.x;
    int i = idx * 2;
    if (i < N_EDGES) {
        int c0, c1;
        if (f64) {
            longlong2 v = ((const longlong2*)((const long long*)ei + N_EDGES))[idx];
            c0 = (int)v.x; c1 = (int)v.y;
        } else {
            int2 v = ((const int2*)((const int*)ei + N_EDGES))[idx];
            c0 = v.x; c1 = v.y;
        }
        g_col[i] = c0; g_col[i + 1] = c1;
        atomicAdd(&g_edeg[c0], 1);          // even slot -> bank 0
        atomicAdd(&g_edeg2[c1], 1);         // odd slot  -> bank 1
    }
}

// ---- side stream: row conversion + batch (only consumers: k_fill / final pool) ----
__global__ void __launch_bounds__(256) k_aux(const void* ei, const void* batch) {
    int f64 = detect64((const unsigned int*)ei);
    int idx = blockIdx.x * 256 + threadIdx.x;
    int i = idx * 2;
    if (i < N_EDGES) {
        int r0, r1;
        if (f64) {
            longlong2 v = ((const longlong2*)ei)[idx];
            r0 = (int)v.x; r1 = (int)v.y;
        } else {
            int2 v = ((const int2*)ei)[idx];
            r0 = v.x; r1 = v.y;
        }
        g_row[i] = r0; g_row[i + 1] = r1;
    }
    if (idx < N_NODES) {
        int b = f64 ? (int)((const long long*)batch)[idx] : ((const int*)batch)[idx];
        g_batch[idx] = b;
    }
}

// ---------------- fused scan: block sums + grid barrier + offsets ----------------
__global__ void __launch_bounds__(256) k_scan() {
    __shared__ int ws[8], ws2[8];
    __shared__ int spre, stot;
    int tid = threadIdx.x, lane = tid & 31, wid = tid >> 5;

    int v = blockIdx.x * 256 + tid;
    int d = (v < N_NODES) ? (g_edeg[v] + g_edeg2[v]) : 0;
    int x = d;
    #pragma unroll
    for (int off = 1; off < 32; off <<= 1) {
        int y = __shfl_up_sync(0xffffffffu, x, off);
        if (lane >= off) x += y;
    }
    if (lane == 31) ws[wid] = x;
    __syncthreads();
    if (tid == 0) {
        int run = 0;
        #pragma unroll
        for (int i = 0; i < 8; i++) { int t = ws[i]; ws2[i] = run; run += t; }
        g_bsum[blockIdx.x] = run;
        __threadfence();
        atomicAdd(&g_scan_cnt, 1);
        while (atomicAdd(&g_scan_cnt, 0) < NBLK) {}
    }
    __syncthreads();

    int bs = (tid < NBLK) ? g_bsum[tid] : 0;
    int mpre = (tid < (int)blockIdx.x) ? bs : 0;
    int mtot = bs;
    #pragma unroll
    for (int off = 16; off > 0; off >>= 1) {
        mpre += __shfl_xor_sync(0xffffffffu, mpre, off);
        mtot += __shfl_xor_sync(0xffffffffu, mtot, off);
    }
    __syncthreads();
    if (lane == 0) { ws[wid] = mpre; }
    __shared__ int wt[8];
    if (lane == 0) { wt[wid] = mtot; }
    __syncthreads();
    if (tid == 0) {
        int a = 0, t = 0;
        #pragma unroll
        for (int i = 0; i < 8; i++) { a += ws[i]; t += wt[i]; }
        spre = a; stot = t;
    }
    __syncthreads();
    if (blockIdx.x == NBLK - 1 && tid == 0) g_off[N_NODES] = stot;

    if (v < N_NODES) {
        int excl = (x - d) + ws2[wid] + spre;
        g_off[v] = excl;
        g_cursor[v] = excl;
        g_dis[v] = rsqrtf((float)(d + 1));
    }
}

// ---- fill CSR (side stream; overlaps layer-1 GEMM) ----
__global__ void __launch_bounds__(256) k_fill() {
    int e = blockIdx.x * 256 + threadIdx.x;
    if (e < N_EDGES) {
        int c = g_col[e];
        int pos = atomicAdd(&g_cursor[c], 1);
        g_csr[pos] = g_row[e];
    }
}

// ---- W prep (side stream) ----
__global__ void __launch_bounds__(256) k_wprep(const float* __restrict__ W_emb,
                                               const float* __restrict__ W_layers) {
    int i = blockIdx.x * 256 + threadIdx.x;
    if (i >= 5 * 128 * 32) return;
    int w = i / (128 * 32), r = i % (128 * 32);
    const float* src = (w == 0) ? W_emb : (W_layers + (w - 1) * 16384);
    float4 a = ((const float4*)src)[r];
    u32 h0 = cvt2(a.y, a.x), h1 = cvt2(a.w, a.z);
    float l0 = a.x - bf_lo(h0), l1 = a.y - bf_hi(h0);
    float l2 = a.z - bf_lo(h1), l3 = a.w - bf_hi(h1);
    u32 q0 = cvt2(l1, l0), q1 = cvt2(l3, l2);
    int base = w * 8192 + r * 2;
    g_Whi[base] = h0; g_Whi[base + 1] = h1;
    g_Wlo[base] = q0; g_Wlo[base + 1] = q1;
}

// ---------------- tensor-core GEMM via mma.sync + ldmatrix ----------------
__global__ void __launch_bounds__(256, 2) k_mma(const float* __restrict__ A,
                                                const u32* __restrict__ Whi,
                                                const u32* __restrict__ Wlo,
                                                const float* __restrict__ bias,
                                                int mode) {
    extern __shared__ u32 smu[];
    u32* sAhi = smu;
    u32* sBhi = smu + 128 * SKW;
    u32* sBlo = smu + 2 * 128 * SKW;

    int tid = threadIdx.x;
    int row0 = blockIdx.x * 128;

    #pragma unroll
    for (int i = 0; i < 16; i++) {
        int f = tid + i * 256;
        int r = f >> 5, c4 = f & 31;
        int gr = row0 + r;
        float4 a = (gr < N_NODES) ? ((const float4*)A)[gr * 32 + c4]
                                  : make_float4(0.f, 0.f, 0.f, 0.f);
        int idx = r * SKW + c4 * 2;
        sAhi[idx]     = cvt2(a.y, a.x);
        sAhi[idx + 1] = cvt2(a.w, a.z);
    }
    #pragma unroll
    for (int i = 0; i < 16; i++) {
        int f = tid + i * 256;
        int o = f >> 5, q = f & 31;
        uint2 vh = ((const uint2*)Whi)[f];
        uint2 vl = ((const uint2*)Wlo)[f];
        int idx = o * SKW + q * 2;
        sBhi[idx] = vh.x; sBhi[idx + 1] = vh.y;
        sBlo[idx] = vl.x; sBlo[idx + 1] = vl.y;
    }
    __syncthreads();

    int lane = tid & 31, warp = tid >> 5;
    int g = lane >> 2, tig = lane & 3;
    int wr = (warp & 3) * 32;
    int wc = (warp >> 2) * 64;

    u32 base = smem_u32(smu);
    u32 aoff0 = (u32)((wr + (lane & 15)) * (SKW * 4) + ((lane >> 4) * 16));
    u32 aoff1 = aoff0 + 16 * (SKW * 4);
    u32 boff[4];
    #pragma unroll
    for (int np = 0; np < 4; np++) {
        int orow = wc + np * 16 + (lane & 7) + ((lane >> 4) & 1) * 8;
        boff[np] = (u32)(orow * (SKW * 4) + (((lane >> 3) & 1) * 16));
    }
    const u32 OF_BHI = 128 * SKW * 4, OF_BLO = 2 * 128 * SKW * 4;

    float acc[2][8][4];
    #pragma unroll
    for (int m = 0; m < 2; m++)
        #pragma unroll
        for (int n = 0; n < 8; n++)
            #pragma unroll
            for (int c = 0; c < 4; c++) acc[m][n][c] = 0.f;

    #pragma unroll
    for (int ks = 0; ks < 8; ks++) {
        u32 kb = ks * 32;
        u32 a[2][4];
        ldm4(a[0][0], a[0][1], a[0][2], a[0][3], base + aoff0 + kb);
        ldm4(a[1][0], a[1][1], a[1][2], a[1][3], base + aoff1 + kb);
        u32 bh[4][4], bl[4][4];
        #pragma unroll
        for (int np = 0; np < 4; np++) {
            ldm4(bh[np][0], bh[np][1], bh[np][2], bh[np][3], base + OF_BHI + boff[np] + kb);
            ldm4(bl[np][0], bl[np][1], bl[np][2], bl[np][3], base + OF_BLO + boff[np] + kb);
        }
        #pragma unroll
        for (int m = 0; m < 2; m++)
            #pragma unroll
            for (int np = 0; np < 4; np++) {
                mma16816(acc[m][2*np][0], acc[m][2*np][1], acc[m][2*np][2], acc[m][2*np][3],
                         a[m][0], a[m][1], a[m][2], a[m][3], bh[np][0], bh[np][1]);
                mma16816(acc[m][2*np+1][0], acc[m][2*np+1][1], acc[m][2*np+1][2], acc[m][2*np+1][3],
                         a[m][0], a[m][1], a[m][2], a[m][3], bh[np][2], bh[np][3]);
                mma16816(acc[m][2*np][0], acc[m][2*np][1], acc[m][2*np][2], acc[m][2*np][3],
                         a[m][0], a[m][1], a[m][2], a[m][3], bl[np][0], bl[np][1]);
                mma16816(acc[m][2*np+1][0], acc[m][2*np+1][1], acc[m][2*np+1][2], acc[m][2*np+1][3],
                         a[m][0], a[m][1], a[m][2], a[m][3], bl[np][2], bl[np][3]);
            }
    }

    #pragma unroll
    for (int m = 0; m < 2; m++) {
        int r0 = row0 + wr + m * 16 + g;
        int r1 = r0 + 8;
        bool ok0 = (r0 < N_NODES), ok1 = (r1 < N_NODES);
        if (mode == 0) {
            #pragma unroll
            for (int n = 0; n < 8; n++) {
                int col = wc + n * 8 + 2 * tig;
                float b0 = bias[col], b1 = bias[col + 1];
                if (ok0) *(float2*)(g_h + r0 * HID + col) =
                    make_float2(acc[m][n][0] + b0, acc[m][n][1] + b1);
                if (ok1) *(float2*)(g_h + r1 * HID + col) =
                    make_float2(acc[m][n][2] + b0, acc[m][n][3] + b1);
            }
        } else {
            float d0 = ok0 ? g_dis[r0] : 0.f;
            float d1 = ok1 ? g_dis[r1] : 0.f;
            #pragma unroll
            for (int n = 0; n < 8; n++) {
                int col = wc + n * 8 + 2 * tig;
                if (ok0) g_tb[r0 * 64 + col / 2] = cvt2(acc[m][n][1] * d0, acc[m][n][0] * d0);
                if (ok1) g_tb[r1 * 64 + col / 2] = cvt2(acc[m][n][3] * d1, acc[m][n][2] * d1);
            }
        }
    }
}

// ------- fused CSR gather (bf16 msgs) + residual + relu + LayerNorm (+pool) -------
__global__ void __launch_bounds__(512) k_gln(const float* __restrict__ b,
                                             const float* __restrict__ gamma,
                                             const float* __restrict__ beta,
                                             const float* __restrict__ Wout) {
    __shared__ float ssum[N_GRAPHS];
    __shared__ int   scnt[N_GRAPHS];
    const bool pool = (Wout != nullptr);
    int tid = threadIdx.x;
    if (pool) {
        if (tid < N_GRAPHS) { ssum[tid] = 0.f; scnt[tid] = 0; }
        __syncthreads();
    }

    int v = (blockIdx.x * blockDim.x + tid) >> 5;
    int lane = tid & 31;
    bool active = (v < N_NODES);
    float4 o = make_float4(0.f, 0.f, 0.f, 0.f);

    if (active) {
        const uint2* T = (const uint2*)g_tb;
        uint2 sv = T[v * 32 + lane];
        float a0 = bf_lo(sv.x), a1 = bf_hi(sv.x), a2 = bf_lo(sv.y), a3 = bf_hi(sv.y);

        int i = g_off[v], e = g_off[v + 1];
        for (; i + 8 <= e; i += 8) {
            int r0 = __ldg(&g_csr[i]);
            int r1 = __ldg(&g_csr[i + 1]);
            int r2 = __ldg(&g_csr[i + 2]);
            int r3 = __ldg(&g_csr[i + 3]);
            int r4 = __ldg(&g_csr[i + 4]);
            int r5 = __ldg(&g_csr[i + 5]);
            int r6 = __ldg(&g_csr[i + 6]);
            int r7 = __ldg(&g_csr[i + 7]);
            uint2 m0 = T[r0 * 32 + lane];
            uint2 m1 = T[r1 * 32 + lane];
            uint2 m2 = T[r2 * 32 + lane];
            uint2 m3 = T[r3 * 32 + lane];
            uint2 m4 = T[r4 * 32 + lane];
            uint2 m5 = T[r5 * 32 + lane];
            uint2 m6 = T[r6 * 32 + lane];
            uint2 m7 = T[r7 * 32 + lane];
            add4(a0, a1, a2, a3, m0); add4(a0, a1, a2, a3, m1);
            add4(a0, a1, a2, a3, m2); add4(a0, a1, a2, a3, m3);
            add4(a0, a1, a2, a3, m4); add4(a0, a1, a2, a3, m5);
            add4(a0, a1, a2, a3, m6); add4(a0, a1, a2, a3, m7);
        }
        for (; i + 4 <= e; i += 4) {
            int r0 = __ldg(&g_csr[i]);
            int r1 = __ldg(&g_csr[i + 1]);
            int r2 = __ldg(&g_csr[i + 2]);
            int r3 = __ldg(&g_csr[i + 3]);
            uint2 m0 = T[r0 * 32 + lane];
            uint2 m1 = T[r1 * 32 + lane];
            uint2 m2 = T[r2 * 32 + lane];
            uint2 m3 = T[r3 * 32 + lane];
            add4(a0, a1, a2, a3, m0); add4(a0, a1, a2, a3, m1);
            add4(a0, a1, a2, a3, m2); add4(a0, a1, a2, a3, m3);
        }
        for (; i < e; i++) {
            int r = __ldg(&g_csr[i]);
            add4(a0, a1, a2, a3, T[r * 32 + lane]);
        }

        float dv = g_dis[v];
        float4 hv = *(const float4*)(g_h + v * HID + lane * 4);
        float4 bv = ((const float4*)b)[lane];
        float x0 = hv.x + fmaxf(dv * a0 + bv.x, 0.f);
        float x1 = hv.y + fmaxf(dv * a1 + bv.y, 0.f);
        float x2 = hv.z + fmaxf(dv * a2 + bv.z, 0.f);
        float x3 = hv.w + fmaxf(dv * a3 + bv.w, 0.f);

        float s = x0 + x1 + x2 + x3;
        #pragma unroll
        for (int off = 16; off > 0; off >>= 1) s += __shfl_xor_sync(0xffffffffu, s, off);
        float mu = s * (1.f / 128.f);
        float d0 = x0 - mu, d1 = x1 - mu, d2 = x2 - mu, d3 = x3 - mu;
        float q = d0 * d0 + d1 * d1 + d2 * d2 + d3 * d3;
        #pragma unroll
        for (int off = 16; off > 0; off >>= 1) q += __shfl_xor_sync(0xffffffffu, q, off);
        float rs = rsqrtf(q * (1.f / 128.f) + LN_EPS);
        float4 gv = ((const float4*)gamma)[lane];
        float4 be = ((const float4*)beta)[lane];
        o.x = d0 * rs * gv.x + be.x;
        o.y = d1 * rs * gv.y + be.y;
        o.z = d2 * rs * gv.z + be.z;
        o.w = d3 * rs * gv.w + be.w;
        *(float4*)(g_h + v * HID + lane * 4) = o;
    }

    if (pool) {
        float s = 0.f;
        if (active) {
            float4 wv = ((const float4*)Wout)[lane];
            s = o.x * wv.x + o.y * wv.y + o.z * wv.z + o.w * wv.w;
        }
        #pragma unroll
        for (int off = 16; off > 0; off >>= 1) s += __shfl_xor_sync(0xffffffffu, s, off);
        if (active && lane == 0) {
            int bg = g_batch[v];
            atomicAdd(&ssum[bg], s);
            atomicAdd(&scnt[bg], 1);
        }
        __syncthreads();
        if (tid < N_GRAPHS && scnt[tid] > 0) {
            atomicAdd(&g_sums[tid], ssum[tid]);
            atomicAdd(&g_cnts[tid], scnt[tid]);
        }
    }
}

// ---- output + state re-zero (both edeg banks, pool accumulators, scan counter) ----
__global__ void __launch_bounds__(256) k_out(float* out) {
    int i = blockIdx.x * 256 + threadIdx.x;
    if (blockIdx.x == 0 && threadIdx.x < N_GRAPHS) {
        int g = threadIdx.x;
        out[g] = g_sums[g] / fmaxf((float)g_cnts[g], 1.f);
        g_sums[g] = 0.f;
        g_cnts[g] = 0;
    }
    if (blockIdx.x == 0 && threadIdx.x == 32) g_scan_cnt = 0;
    if (i < N_NODES) { g_edeg[i] = 0; g_edeg2[i] = 0; }
}

// ---------------- launch ----------------
extern "C" void kernel_launch(void* const* d_in, const int* in_sizes, int n_in,
                              void* d_out, int out_size) {
    const float* x        = (const float*)d_in[0];
    const void*  ei       = d_in[1];
    const void*  batch    = d_in[2];
    const float* W_emb    = (const float*)d_in[3];
    const float* b_emb    = (const float*)d_in[4];
    const float* W_layers = (const float*)d_in[5];
    const float* b_layers = (const float*)d_in[6];
    const float* ln_gamma = (const float*)d_in[7];
    const float* ln_beta  = (const float*)d_in[8];
    const float* W_out    = (const float*)d_in[9];
    float* out = (float*)d_out;

    const int MMA_SMEM = 3 * 128 * SKW * sizeof(u32);   // 104,448 B -> 2 CTAs/SM
    static cudaStream_t s2 = nullptr;
    static cudaEvent_t evA = nullptr, evB = nullptr, evC = nullptr, evD = nullptr;
    if (!s2) {
        cudaFuncSetAttribute(k_mma, cudaFuncAttributeMaxDynamicSharedMemorySize, MMA_SMEM);
        cudaStreamCreateWithFlags(&s2, cudaStreamNonBlocking);
        cudaEventCreateWithFlags(&evA, cudaEventDisableTiming);
        cudaEventCreateWithFlags(&evB, cudaEventDisableTiming);
        cudaEventCreateWithFlags(&evC, cudaEventDisableTiming);
        cudaEventCreateWithFlags(&evD, cudaEventDisableTiming);
    }

    float* d_h = nullptr;
    cudaGetSymbolAddress((void**)&d_h, g_h);
    u32* whi = nullptr;
    cudaGetSymbolAddress((void**)&whi, g_Whi);
    u32* wlo = nullptr;
    cudaGetSymbolAddress((void**)&wlo, g_Wlo);

    // fork: side stream does W prep + embedding GEMM + row/batch convert
    cudaEventRecord(evA, 0);
    cudaStreamWaitEvent(s2, evA, 0);
    k_wprep<<<WPBLK, 256, 0, s2>>>(W_emb, W_layers);
    k_mma<<<MMA_BLOCKS, 256, MMA_SMEM, s2>>>(x, whi, wlo, b_emb, 0);
    cudaEventRecord(evB, s2);
    k_aux<<<EBLK2, 256, 0, s2>>>(ei, batch);

    // main stream: critical-path preamble (col+deg -> fused scan)
    k_deg<<<EBLK2, 256>>>(ei);
    k_scan<<<NBLK, 256>>>();
    cudaEventRecord(evC, 0);

    // side stream: CSR fill (needs aux rows + scan cursors), overlaps layer-1 GEMM
    cudaStreamWaitEvent(s2, evC, 0);
    k_fill<<<EBLK2 * 2, 256, 0, s2>>>();
    cudaEventRecord(evD, s2);

    cudaStreamWaitEvent(0, evB, 0);       // embedding result ready

    int gln_blocks = (N_NODES + 15) / 16;    // 3125
    for (int i = 0; i < 4; i++) {
        k_mma<<<MMA_BLOCKS, 256, MMA_SMEM>>>(d_h, whi + (1 + i) * 8192, wlo + (1 + i) * 8192,
                                             nullptr, 1);
        if (i == 0) cudaStreamWaitEvent(0, evD, 0);   // CSR ready before first gather
        k_gln<<<gln_blocks, 512>>>(b_layers + i * HID, ln_gamma + i * HID, ln_beta + i * HID,
                                   (i == 3) ? W_out : nullptr);
    }

    k_out<<<NBLK, 256>>>(out);
}

// round 16
// speedup vs baseline: 1.0172x; 1.0172x over previous
#include <cuda_runtime.h>
#include <cstdint>

#define N_NODES 50000
#define N_EDGES 800000
#define HID     128
#define N_GRAPHS 32
#define LN_EPS  1e-5f
#define NBLK    196                         // ceil(50000/256)
#define EBLK2   1563                        // ceil(800000/2/256)
#define WPBLK   80                          // ceil(5*128*32/256)
#define MMA_BLOCKS ((N_NODES + 127) / 128)  // 391
#define SKW 68                              // smem row stride in u32 (272B)

typedef unsigned int u32;

// ---------------- scratch (device globals; zero-initialized at load) ----------------
__device__ __align__(16) u32 g_h[N_NODES * HID / 2];    // h as bf16x2 (mma uses bf16(h) anyway)
__device__ __align__(16) u32 g_tb[N_NODES * HID / 2];   // t' as bf16x2
__device__ __align__(16) u32 g_Whi[5 * HID * HID / 2];  // W bf16 hi, [o][k] pairs
__device__ __align__(16) u32 g_Wlo[5 * HID * HID / 2];  // W bf16 lo
__device__ float g_dis[N_NODES];
__device__ int   g_edeg[N_NODES];           // ZEROED at end of every launch (and at load)
__device__ int   g_off[N_NODES + 1];
__device__ int   g_cursor[N_NODES];
__device__ int   g_csr[N_EDGES];
__device__ int   g_row[N_EDGES];
__device__ int   g_col[N_EDGES];
__device__ int   g_batch[N_NODES];
__device__ int   g_bsum[NBLK];
__device__ int   g_scan_cnt;                // ZEROED at end of every launch
__device__ float g_sums[N_GRAPHS];          // ZEROED at end of every launch
__device__ int   g_cnts[N_GRAPHS];          // ZEROED at end of every launch

// ---------------- helpers ----------------
__device__ __forceinline__ u32 cvt2(float hi_elem, float lo_elem) {
    u32 r; asm("cvt.rn.bf16x2.f32 %0, %1, %2;" : "=r"(r) : "f"(hi_elem), "f"(lo_elem)); return r;
}
__device__ __forceinline__ float bf_lo(u32 v) { return __uint_as_float(v << 16); }
__device__ __forceinline__ float bf_hi(u32 v) { return __uint_as_float(v & 0xffff0000u); }

__device__ __forceinline__ u32 smem_u32(const void* p) {
    u32 a;
    asm("{ .reg .u64 t; cvta.to.shared.u64 t, %1; cvt.u32.u64 %0, t; }" : "=r"(a) : "l"(p));
    return a;
}
__device__ __forceinline__ void ldm4(u32& r0, u32& r1, u32& r2, u32& r3, u32 addr) {
    asm volatile("ldmatrix.sync.aligned.m8n8.x4.shared.b16 {%0,%1,%2,%3}, [%4];"
                 : "=r"(r0), "=r"(r1), "=r"(r2), "=r"(r3) : "r"(addr));
}
__device__ __forceinline__ void mma16816(float& c0, float& c1, float& c2, float& c3,
                                         u32 a0, u32 a1, u32 a2, u32 a3, u32 b0, u32 b1) {
    asm volatile(
        "mma.sync.aligned.m16n8k16.row.col.f32.bf16.bf16.f32 "
        "{%0,%1,%2,%3}, {%4,%5,%6,%7}, {%8,%9}, {%0,%1,%2,%3};"
        : "+f"(c0), "+f"(c1), "+f"(c2), "+f"(c3)
        : "r"(a0), "r"(a1), "r"(a2), "r"(a3), "r"(b0), "r"(b1));
}
__device__ __forceinline__ void add4(float& a0, float& a1, float& a2, float& a3, uint2 m) {
    a0 += bf_lo(m.x); a1 += bf_hi(m.x); a2 += bf_lo(m.y); a3 += bf_hi(m.y);
}
__device__ __forceinline__ int detect64(const unsigned int* w) {
    __shared__ int sflag;
    if (threadIdx.x < 32) {
        unsigned ok = 1;
        #pragma unroll
        for (int j = 0; j < 4; j++) ok &= (w[1 + 2 * (threadIdx.x * 4 + j)] == 0u);
        unsigned all = __ballot_sync(0xffffffffu, ok != 0);
        if (threadIdx.x == 0) sflag = (all == 0xffffffffu);
    }
    __syncthreads();
    return sflag;
}

// ---- critical path: col conversion + degree atomics (2 edges/thread, 16B loads) ----
__global__ void __launch_bounds__(256) k_deg(const void* ei) {
    int f64 = detect64((const unsigned int*)ei);
    int idx = blockIdx.x * 256 + threadIdx.x;
    int i = idx * 2;
    if (i < N_EDGES) {
        int c0, c1;
        if (f64) {
            longlong2 v = ((const longlong2*)((const long long*)ei + N_EDGES))[idx];
            c0 = (int)v.x; c1 = (int)v.y;
        } else {
            int2 v = ((const int2*)((const int*)ei + N_EDGES))[idx];
            c0 = v.x; c1 = v.y;
        }
        g_col[i] = c0; g_col[i + 1] = c1;
        atomicAdd(&g_edeg[c0], 1);
        atomicAdd(&g_edeg[c1], 1);
    }
}

// ---- side stream: row conversion + batch ----
__global__ void __launch_bounds__(256) k_aux(const void* ei, const void* batch) {
    int f64 = detect64((const unsigned int*)ei);
    int idx = blockIdx.x * 256 + threadIdx.x;
    int i = idx * 2;
    if (i < N_EDGES) {
        int r0, r1;
        if (f64) {
            longlong2 v = ((const longlong2*)ei)[idx];
            r0 = (int)v.x; r1 = (int)v.y;
        } else {
            int2 v = ((const int2*)ei)[idx];
            r0 = v.x; r1 = v.y;
        }
        g_row[i] = r0; g_row[i + 1] = r1;
    }
    if (idx < N_NODES) {
        int b = f64 ? (int)((const long long*)batch)[idx] : ((const int*)batch)[idx];
        g_batch[idx] = b;
    }
}

// ---------------- fused scan: block sums + grid barrier + offsets ----------------
__global__ void __launch_bounds__(256) k_scan() {
    __shared__ int ws[8], ws2[8];
    __shared__ int spre, stot;
    int tid = threadIdx.x, lane = tid & 31, wid = tid >> 5;

    int v = blockIdx.x * 256 + tid;
    int d = (v < N_NODES) ? g_edeg[v] : 0;
    int x = d;
    #pragma unroll
    for (int off = 1; off < 32; off <<= 1) {
        int y = __shfl_up_sync(0xffffffffu, x, off);
        if (lane >= off) x += y;
    }
    if (lane == 31) ws[wid] = x;
    __syncthreads();
    if (tid == 0) {
        int run = 0;
        #pragma unroll
        for (int i = 0; i < 8; i++) { int t = ws[i]; ws2[i] = run; run += t; }
        g_bsum[blockIdx.x] = run;
        __threadfence();
        atomicAdd(&g_scan_cnt, 1);
        while (atomicAdd(&g_scan_cnt, 0) < NBLK) {}
    }
    __syncthreads();

    int bs = (tid < NBLK) ? g_bsum[tid] : 0;
    int mpre = (tid < (int)blockIdx.x) ? bs : 0;
    int mtot = bs;
    #pragma unroll
    for (int off = 16; off > 0; off >>= 1) {
        mpre += __shfl_xor_sync(0xffffffffu, mpre, off);
        mtot += __shfl_xor_sync(0xffffffffu, mtot, off);
    }
    __syncthreads();
    if (lane == 0) { ws[wid] = mpre; }
    __shared__ int wt[8];
    if (lane == 0) { wt[wid] = mtot; }
    __syncthreads();
    if (tid == 0) {
        int a = 0, t = 0;
        #pragma unroll
        for (int i = 0; i < 8; i++) { a += ws[i]; t += wt[i]; }
        spre = a; stot = t;
    }
    __syncthreads();
    if (blockIdx.x == NBLK - 1 && tid == 0) g_off[N_NODES] = stot;

    if (v < N_NODES) {
        int excl = (x - d) + ws2[wid] + spre;
        g_off[v] = excl;
        g_cursor[v] = excl;
        g_dis[v] = rsqrtf((float)(d + 1));
    }
}

// ---- fill CSR (side stream; overlaps layer-1 GEMM) ----
__global__ void __launch_bounds__(256) k_fill() {
    int e = blockIdx.x * 256 + threadIdx.x;
    if (e < N_EDGES) {
        int c = g_col[e];
        int pos = atomicAdd(&g_cursor[c], 1);
        g_csr[pos] = g_row[e];
    }
}

// ---- W prep (side stream) ----
__global__ void __launch_bounds__(256) k_wprep(const float* __restrict__ W_emb,
                                               const float* __restrict__ W_layers) {
    int i = blockIdx.x * 256 + threadIdx.x;
    if (i >= 5 * 128 * 32) return;
    int w = i / (128 * 32), r = i % (128 * 32);
    const float* src = (w == 0) ? W_emb : (W_layers + (w - 1) * 16384);
    float4 a = ((const float4*)src)[r];
    u32 h0 = cvt2(a.y, a.x), h1 = cvt2(a.w, a.z);
    float l0 = a.x - bf_lo(h0), l1 = a.y - bf_hi(h0);
    float l2 = a.z - bf_lo(h1), l3 = a.w - bf_hi(h1);
    u32 q0 = cvt2(l1, l0), q1 = cvt2(l3, l2);
    int base = w * 8192 + r * 2;
    g_Whi[base] = h0; g_Whi[base + 1] = h1;
    g_Wlo[base] = q0; g_Wlo[base + 1] = q1;
}

// ---------------- tensor-core GEMM via mma.sync + ldmatrix ----------------
// mode 0: A = x (fp32), out = g_h = bf16x2(A W^T + bias)
// mode 1: A = g_h (bf16x2), out = g_tb = bf16x2(dis[row] * (A W^T))
__global__ void __launch_bounds__(256, 2) k_mma(const void* __restrict__ A,
                                                const u32* __restrict__ Whi,
                                                const u32* __restrict__ Wlo,
                                                const float* __restrict__ bias,
                                                int mode) {
    extern __shared__ u32 smu[];
    u32* sAhi = smu;
    u32* sBhi = smu + 128 * SKW;
    u32* sBlo = smu + 2 * 128 * SKW;

    int tid = threadIdx.x;
    int row0 = blockIdx.x * 128;

    if (mode == 0) {
        // stage A from fp32 x, converting to bf16 (hi only)
        const float4* Af = (const float4*)A;
        #pragma unroll
        for (int i = 0; i < 16; i++) {
            int f = tid + i * 256;
            int r = f >> 5, c4 = f & 31;
            int gr = row0 + r;
            float4 a = (gr < N_NODES) ? Af[gr * 32 + c4]
                                      : make_float4(0.f, 0.f, 0.f, 0.f);
            int idx = r * SKW + c4 * 2;
            sAhi[idx]     = cvt2(a.y, a.x);
            sAhi[idx + 1] = cvt2(a.w, a.z);
        }
    } else {
        // stage A from bf16x2 g_h: raw copy (half the bytes, no cvt)
        const uint2* Ab = (const uint2*)A;
        #pragma unroll
        for (int i = 0; i < 16; i++) {
            int f = tid + i * 256;                   // 4096 uint2 over 128x64 u32
            int r = f >> 5, q = f & 31;
            int gr = row0 + r;
            uint2 v = (gr < N_NODES) ? Ab[gr * 32 + q] : make_uint2(0u, 0u);
            int idx = r * SKW + q * 2;
            sAhi[idx] = v.x; sAhi[idx + 1] = v.y;
        }
    }
    #pragma unroll
    for (int i = 0; i < 16; i++) {
        int f = tid + i * 256;
        int o = f >> 5, q = f & 31;
        uint2 vh = ((const uint2*)Whi)[f];
        uint2 vl = ((const uint2*)Wlo)[f];
        int idx = o * SKW + q * 2;
        sBhi[idx] = vh.x; sBhi[idx + 1] = vh.y;
        sBlo[idx] = vl.x; sBlo[idx + 1] = vl.y;
    }
    __syncthreads();

    int lane = tid & 31, warp = tid >> 5;
    int g = lane >> 2, tig = lane & 3;
    int wr = (warp & 3) * 32;
    int wc = (warp >> 2) * 64;

    u32 base = smem_u32(smu);
    u32 aoff0 = (u32)((wr + (lane & 15)) * (SKW * 4) + ((lane >> 4) * 16));
    u32 aoff1 = aoff0 + 16 * (SKW * 4);
    u32 boff[4];
    #pragma unroll
    for (int np = 0; np < 4; np++) {
        int orow = wc + np * 16 + (lane & 7) + ((lane >> 4) & 1) * 8;
        boff[np] = (u32)(orow * (SKW * 4) + (((lane >> 3) & 1) * 16));
    }
    const u32 OF_BHI = 128 * SKW * 4, OF_BLO = 2 * 128 * SKW * 4;

    float acc[2][8][4];
    #pragma unroll
    for (int m = 0; m < 2; m++)
        #pragma unroll
        for (int n = 0; n < 8; n++)
            #pragma unroll
            for (int c = 0; c < 4; c++) acc[m][n][c] = 0.f;

    #pragma unroll
    for (int ks = 0; ks < 8; ks++) {
        u32 kb = ks * 32;
        u32 a[2][4];
        ldm4(a[0][0], a[0][1], a[0][2], a[0][3], base + aoff0 + kb);
        ldm4(a[1][0], a[1][1], a[1][2], a[1][3], base + aoff1 + kb);
        u32 bh[4][4], bl[4][4];
        #pragma unroll
        for (int np = 0; np < 4; np++) {
            ldm4(bh[np][0], bh[np][1], bh[np][2], bh[np][3], base + OF_BHI + boff[np] + kb);
            ldm4(bl[np][0], bl[np][1], bl[np][2], bl[np][3], base + OF_BLO + boff[np] + kb);
        }
        #pragma unroll
        for (int m = 0; m < 2; m++)
            #pragma unroll
            for (int np = 0; np < 4; np++) {
                mma16816(acc[m][2*np][0], acc[m][2*np][1], acc[m][2*np][2], acc[m][2*np][3],
                         a[m][0], a[m][1], a[m][2], a[m][3], bh[np][0], bh[np][1]);
                mma16816(acc[m][2*np+1][0], acc[m][2*np+1][1], acc[m][2*np+1][2], acc[m][2*np+1][3],
                         a[m][0], a[m][1], a[m][2], a[m][3], bh[np][2], bh[np][3]);
                mma16816(acc[m][2*np][0], acc[m][2*np][1], acc[m][2*np][2], acc[m][2*np][3],
                         a[m][0], a[m][1], a[m][2], a[m][3], bl[np][0], bl[np][1]);
                mma16816(acc[m][2*np+1][0], acc[m][2*np+1][1], acc[m][2*np+1][2], acc[m][2*np+1][3],
                         a[m][0], a[m][1], a[m][2], a[m][3], bl[np][2], bl[np][3]);
            }
    }

    #pragma unroll
    for (int m = 0; m < 2; m++) {
        int r0 = row0 + wr + m * 16 + g;
        int r1 = r0 + 8;
        bool ok0 = (r0 < N_NODES), ok1 = (r1 < N_NODES);
        if (mode == 0) {
            #pragma unroll
            for (int n = 0; n < 8; n++) {
                int col = wc + n * 8 + 2 * tig;
                float b0 = bias[col], b1 = bias[col + 1];
                if (ok0) g_h[r0 * 64 + col / 2] = cvt2(acc[m][n][1] + b1, acc[m][n][0] + b0);
                if (ok1) g_h[r1 * 64 + col / 2] = cvt2(acc[m][n][3] + b1, acc[m][n][2] + b0);
            }
        } else {
            float d0 = ok0 ? g_dis[r0] : 0.f;
            float d1 = ok1 ? g_dis[r1] : 0.f;
            #pragma unroll
            for (int n = 0; n < 8; n++) {
                int col = wc + n * 8 + 2 * tig;
                if (ok0) g_tb[r0 * 64 + col / 2] = cvt2(acc[m][n][1] * d0, acc[m][n][0] * d0);
                if (ok1) g_tb[r1 * 64 + col / 2] = cvt2(acc[m][n][3] * d1, acc[m][n][2] * d1);
            }
        }
    }
}

// ------- fused CSR gather (bf16 msgs) + residual + relu + LayerNorm (+pool) -------
__global__ void __launch_bounds__(512) k_gln(const float* __restrict__ b,
                                             const float* __restrict__ gamma,
                                             const float* __restrict__ beta,
                                             const float* __restrict__ Wout) {
    __shared__ float ssum[N_GRAPHS];
    __shared__ int   scnt[N_GRAPHS];
    const bool pool = (Wout != nullptr);
    int tid = threadIdx.x;
    if (pool) {
        if (tid < N_GRAPHS) { ssum[tid] = 0.f; scnt[tid] = 0; }
        __syncthreads();
    }

    int v = (blockIdx.x * blockDim.x + tid) >> 5;
    int lane = tid & 31;
    bool active = (v < N_NODES);
    float4 o = make_float4(0.f, 0.f, 0.f, 0.f);

    if (active) {
        const uint2* T = (const uint2*)g_tb;
        uint2 sv = T[v * 32 + lane];
        float a0 = bf_lo(sv.x), a1 = bf_hi(sv.x), a2 = bf_lo(sv.y), a3 = bf_hi(sv.y);

        int i = g_off[v], e = g_off[v + 1];
        for (; i + 8 <= e; i += 8) {
            int r0 = __ldg(&g_csr[i]);
            int r1 = __ldg(&g_csr[i + 1]);
            int r2 = __ldg(&g_csr[i + 2]);
            int r3 = __ldg(&g_csr[i + 3]);
            int r4 = __ldg(&g_csr[i + 4]);
            int r5 = __ldg(&g_csr[i + 5]);
            int r6 = __ldg(&g_csr[i + 6]);
            int r7 = __ldg(&g_csr[i + 7]);
            uint2 m0 = T[r0 * 32 + lane];
            uint2 m1 = T[r1 * 32 + lane];
            uint2 m2 = T[r2 * 32 + lane];
            uint2 m3 = T[r3 * 32 + lane];
            uint2 m4 = T[r4 * 32 + lane];
            uint2 m5 = T[r5 * 32 + lane];
            uint2 m6 = T[r6 * 32 + lane];
            uint2 m7 = T[r7 * 32 + lane];
            add4(a0, a1, a2, a3, m0); add4(a0, a1, a2, a3, m1);
            add4(a0, a1, a2, a3, m2); add4(a0, a1, a2, a3, m3);
            add4(a0, a1, a2, a3, m4); add4(a0, a1, a2, a3, m5);
            add4(a0, a1, a2, a3, m6); add4(a0, a1, a2, a3, m7);
        }
        for (; i + 4 <= e; i += 4) {
            int r0 = __ldg(&g_csr[i]);
            int r1 = __ldg(&g_csr[i + 1]);
            int r2 = __ldg(&g_csr[i + 2]);
            int r3 = __ldg(&g_csr[i + 3]);
            uint2 m0 = T[r0 * 32 + lane];
            uint2 m1 = T[r1 * 32 + lane];
            uint2 m2 = T[r2 * 32 + lane];
            uint2 m3 = T[r3 * 32 + lane];
            add4(a0, a1, a2, a3, m0); add4(a0, a1, a2, a3, m1);
            add4(a0, a1, a2, a3, m2); add4(a0, a1, a2, a3, m3);
        }
        for (; i < e; i++) {
            int r = __ldg(&g_csr[i]);
            add4(a0, a1, a2, a3, T[r * 32 + lane]);
        }

        float dv = g_dis[v];
        uint2 hb = ((const uint2*)g_h)[v * 32 + lane];
        float h0 = bf_lo(hb.x), h1 = bf_hi(hb.x), h2 = bf_lo(hb.y), h3 = bf_hi(hb.y);
        float4 bv = ((const float4*)b)[lane];
        float x0 = h0 + fmaxf(dv * a0 + bv.x, 0.f);
        float x1 = h1 + fmaxf(dv * a1 + bv.y, 0.f);
        float x2 = h2 + fmaxf(dv * a2 + bv.z, 0.f);
        float x3 = h3 + fmaxf(dv * a3 + bv.w, 0.f);

        float s = x0 + x1 + x2 + x3;
        #pragma unroll
        for (int off = 16; off > 0; off >>= 1) s += __shfl_xor_sync(0xffffffffu, s, off);
        float mu = s * (1.f / 128.f);
        float d0 = x0 - mu, d1 = x1 - mu, d2 = x2 - mu, d3 = x3 - mu;
        float q = d0 * d0 + d1 * d1 + d2 * d2 + d3 * d3;
        #pragma unroll
        for (int off = 16; off > 0; off >>= 1) q += __shfl_xor_sync(0xffffffffu, q, off);
        float rs = rsqrtf(q * (1.f / 128.f) + LN_EPS);
        float4 gv = ((const float4*)gamma)[lane];
        float4 be = ((const float4*)beta)[lane];
        o.x = d0 * rs * gv.x + be.x;
        o.y = d1 * rs * gv.y + be.y;
        o.z = d2 * rs * gv.z + be.z;
        o.w = d3 * rs * gv.w + be.w;
        uint2 ho;
        ho.x = cvt2(o.y, o.x);
        ho.y = cvt2(o.w, o.z);
        ((uint2*)g_h)[v * 32 + lane] = ho;
    }

    if (pool) {
        float s = 0.f;
        if (active) {
            float4 wv = ((const float4*)Wout)[lane];
            s = o.x * wv.x + o.y * wv.y + o.z * wv.z + o.w * wv.w;
        }
        #pragma unroll
        for (int off = 16; off > 0; off >>= 1) s += __shfl_xor_sync(0xffffffffu, s, off);
        if (active && lane == 0) {
            int bg = g_batch[v];
            atomicAdd(&ssum[bg], s);
            atomicAdd(&scnt[bg], 1);
        }
        __syncthreads();
        if (tid < N_GRAPHS && scnt[tid] > 0) {
            atomicAdd(&g_sums[tid], ssum[tid]);
            atomicAdd(&g_cnts[tid], scnt[tid]);
        }
    }
}

// ---- output + state re-zero (edeg, pool accumulators, scan counter) ----
__global__ void __launch_bounds__(256) k_out(float* out) {
    int i = blockIdx.x * 256 + threadIdx.x;
    if (blockIdx.x == 0 && threadIdx.x < N_GRAPHS) {
        int g = threadIdx.x;
        out[g] = g_sums[g] / fmaxf((float)g_cnts[g], 1.f);
        g_sums[g] = 0.f;
        g_cnts[g] = 0;
    }
    if (blockIdx.x == 0 && threadIdx.x == 32) g_scan_cnt = 0;
    if (i < N_NODES) g_edeg[i] = 0;
}

// ---------------- launch ----------------
extern "C" void kernel_launch(void* const* d_in, const int* in_sizes, int n_in,
                              void* d_out, int out_size) {
    const float* x        = (const float*)d_in[0];
    const void*  ei       = d_in[1];
    const void*  batch    = d_in[2];
    const float* W_emb    = (const float*)d_in[3];
    const float* b_emb    = (const float*)d_in[4];
    const float* W_layers = (const float*)d_in[5];
    const float* b_layers = (const float*)d_in[6];
    const float* ln_gamma = (const float*)d_in[7];
    const float* ln_beta  = (const float*)d_in[8];
    const float* W_out    = (const float*)d_in[9];
    float* out = (float*)d_out;

    const int MMA_SMEM = 3 * 128 * SKW * sizeof(u32);   // 104,448 B -> 2 CTAs/SM
    static cudaStream_t s2 = nullptr;
    static cudaEvent_t evA = nullptr, evB = nullptr, evC = nullptr, evD = nullptr;
    if (!s2) {
        cudaFuncSetAttribute(k_mma, cudaFuncAttributeMaxDynamicSharedMemorySize, MMA_SMEM);
        cudaStreamCreateWithFlags(&s2, cudaStreamNonBlocking);
        cudaEventCreateWithFlags(&evA, cudaEventDisableTiming);
        cudaEventCreateWithFlags(&evB, cudaEventDisableTiming);
        cudaEventCreateWithFlags(&evC, cudaEventDisableTiming);
        cudaEventCreateWithFlags(&evD, cudaEventDisableTiming);
    }

    u32* d_h = nullptr;
    cudaGetSymbolAddress((void**)&d_h, g_h);
    u32* whi = nullptr;
    cudaGetSymbolAddress((void**)&whi, g_Whi);
    u32* wlo = nullptr;
    cudaGetSymbolAddress((void**)&wlo, g_Wlo);

    // fork: side stream does W prep + embedding GEMM + row/batch convert
    cudaEventRecord(evA, 0);
    cudaStreamWaitEvent(s2, evA, 0);
    k_wprep<<<WPBLK, 256, 0, s2>>>(W_emb, W_layers);
    k_mma<<<MMA_BLOCKS, 256, MMA_SMEM, s2>>>(x, whi, wlo, b_emb, 0);
    cudaEventRecord(evB, s2);
    k_aux<<<EBLK2, 256, 0, s2>>>(ei, batch);

    // main stream: critical-path preamble (col+deg -> fused scan)
    k_deg<<<EBLK2, 256>>>(ei);
    k_scan<<<NBLK, 256>>>();
    cudaEventRecord(evC, 0);

    // side stream: CSR fill (needs aux rows + scan cursors), overlaps layer-1 GEMM
    cudaStreamWaitEvent(s2, evC, 0);
    k_fill<<<EBLK2 * 2, 256, 0, s2>>>();
    cudaEventRecord(evD, s2);

    cudaStreamWaitEvent(0, evB, 0);       // embedding result ready

    int gln_blocks = (N_NODES + 15) / 16;    // 3125
    for (int i = 0; i < 4; i++) {
        k_mma<<<MMA_BLOCKS, 256, MMA_SMEM>>>(d_h, whi + (1 + i) * 8192, wlo + (1 + i) * 8192,
                                             nullptr, 1);
        if (i == 0) cudaStreamWaitEvent(0, evD, 0);   // CSR ready before first gather
        k_gln<<<gln_blocks, 512>>>(b_layers + i * HID, ln_gamma + i * HID, ln_beta + i * HID,
                                   (i == 3) ? W_out : nullptr);
    }

    k_out<<<NBLK, 256>>>(out);
}

// round 17
// speedup vs baseline: 1.0290x; 1.0116x over previous
#include <cuda_runtime.h>
#include <cstdint>

#define N_NODES 50000
#define N_EDGES 800000
#define HID     128
#define N_GRAPHS 32
#define LN_EPS  1e-5f
#define NBLK    196                         // ceil(50000/256)
#define EBLK2   1563                        // ceil(800000/2/256)
#define WPBLK   80                          // ceil(5*128*32/256)
#define MMA_TILES ((N_NODES + 127) / 128)   // 391
#define MMA_GRID  296                       // 2 CTAs/SM x 148 SMs (persistent, no tail wave)
#define SKW 68                              // smem row stride in u32 (272B)

typedef unsigned int u32;

// ---------------- scratch (device globals; zero-initialized at load) ----------------
__device__ __align__(16) u32 g_h[N_NODES * HID / 2];    // h as bf16x2
__device__ __align__(16) u32 g_tb[N_NODES * HID / 2];   // t' as bf16x2
__device__ __align__(16) u32 g_Whi[5 * HID * HID / 2];  // W bf16 hi, [o][k] pairs
__device__ __align__(16) u32 g_Wlo[5 * HID * HID / 2];  // W bf16 lo
__device__ float g_dis[N_NODES];
__device__ int   g_edeg[N_NODES];           // ZEROED at end of every launch (and at load)
__device__ int   g_off[N_NODES + 1];
__device__ int   g_cursor[N_NODES];
__device__ int   g_csr[N_EDGES];
__device__ int   g_row[N_EDGES];
__device__ int   g_col[N_EDGES];
__device__ int   g_batch[N_NODES];
__device__ int   g_bsum[NBLK];
__device__ int   g_scan_cnt;                // ZEROED at end of every launch
__device__ float g_sums[N_GRAPHS];          // ZEROED at end of every launch
__device__ int   g_cnts[N_GRAPHS];          // ZEROED at end of every launch

// ---------------- helpers ----------------
__device__ __forceinline__ u32 cvt2(float hi_elem, float lo_elem) {
    u32 r; asm("cvt.rn.bf16x2.f32 %0, %1, %2;" : "=r"(r) : "f"(hi_elem), "f"(lo_elem)); return r;
}
__device__ __forceinline__ float bf_lo(u32 v) { return __uint_as_float(v << 16); }
__device__ __forceinline__ float bf_hi(u32 v) { return __uint_as_float(v & 0xffff0000u); }

__device__ __forceinline__ u32 smem_u32(const void* p) {
    u32 a;
    asm("{ .reg .u64 t; cvta.to.shared.u64 t, %1; cvt.u32.u64 %0, t; }" : "=r"(a) : "l"(p));
    return a;
}
__device__ __forceinline__ void ldm4(u32& r0, u32& r1, u32& r2, u32& r3, u32 addr) {
    asm volatile("ldmatrix.sync.aligned.m8n8.x4.shared.b16 {%0,%1,%2,%3}, [%4];"
                 : "=r"(r0), "=r"(r1), "=r"(r2), "=r"(r3) : "r"(addr));
}
__device__ __forceinline__ void mma16816(float& c0, float& c1, float& c2, float& c3,
                                         u32 a0, u32 a1, u32 a2, u32 a3, u32 b0, u32 b1) {
    asm volatile(
        "mma.sync.aligned.m16n8k16.row.col.f32.bf16.bf16.f32 "
        "{%0,%1,%2,%3}, {%4,%5,%6,%7}, {%8,%9}, {%0,%1,%2,%3};"
        : "+f"(c0), "+f"(c1), "+f"(c2), "+f"(c3)
        : "r"(a0), "r"(a1), "r"(a2), "r"(a3), "r"(b0), "r"(b1));
}
__device__ __forceinline__ void add4(float& a0, float& a1, float& a2, float& a3, uint2 m) {
    a0 += bf_lo(m.x); a1 += bf_hi(m.x); a2 += bf_lo(m.y); a3 += bf_hi(m.y);
}
__device__ __forceinline__ int detect64(const unsigned int* w) {
    __shared__ int sflag;
    if (threadIdx.x < 32) {
        unsigned ok = 1;
        #pragma unroll
        for (int j = 0; j < 4; j++) ok &= (w[1 + 2 * (threadIdx.x * 4 + j)] == 0u);
        unsigned all = __ballot_sync(0xffffffffu, ok != 0);
        if (threadIdx.x == 0) sflag = (all == 0xffffffffu);
    }
    __syncthreads();
    return sflag;
}

// ---- critical path: col conversion + degree atomics (2 edges/thread, 16B loads) ----
__global__ void __launch_bounds__(256) k_deg(const void* ei) {
    int f64 = detect64((const unsigned int*)ei);
    int idx = blockIdx.x * 256 + threadIdx.x;
    int i = idx * 2;
    if (i < N_EDGES) {
        int c0, c1;
        if (f64) {
            longlong2 v = ((const longlong2*)((const long long*)ei + N_EDGES))[idx];
            c0 = (int)v.x; c1 = (int)v.y;
        } else {
            int2 v = ((const int2*)((const int*)ei + N_EDGES))[idx];
            c0 = v.x; c1 = v.y;
        }
        g_col[i] = c0; g_col[i + 1] = c1;
        atomicAdd(&g_edeg[c0], 1);
        atomicAdd(&g_edeg[c1], 1);
    }
}

// ---- side stream: row conversion + batch ----
__global__ void __launch_bounds__(256) k_aux(const void* ei, const void* batch) {
    int f64 = detect64((const unsigned int*)ei);
    int idx = blockIdx.x * 256 + threadIdx.x;
    int i = idx * 2;
    if (i < N_EDGES) {
        int r0, r1;
        if (f64) {
            longlong2 v = ((const longlong2*)ei)[idx];
            r0 = (int)v.x; r1 = (int)v.y;
        } else {
            int2 v = ((const int2*)ei)[idx];
            r0 = v.x; r1 = v.y;
        }
        g_row[i] = r0; g_row[i + 1] = r1;
    }
    if (idx < N_NODES) {
        int b = f64 ? (int)((const long long*)batch)[idx] : ((const int*)batch)[idx];
        g_batch[idx] = b;
    }
}

// ---------------- fused scan: block sums + grid barrier + offsets ----------------
__global__ void __launch_bounds__(256) k_scan() {
    __shared__ int ws[8], ws2[8];
    __shared__ int spre, stot;
    int tid = threadIdx.x, lane = tid & 31, wid = tid >> 5;

    int v = blockIdx.x * 256 + tid;
    int d = (v < N_NODES) ? g_edeg[v] : 0;
    int x = d;
    #pragma unroll
    for (int off = 1; off < 32; off <<= 1) {
        int y = __shfl_up_sync(0xffffffffu, x, off);
        if (lane >= off) x += y;
    }
    if (lane == 31) ws[wid] = x;
    __syncthreads();
    if (tid == 0) {
        int run = 0;
        #pragma unroll
        for (int i = 0; i < 8; i++) { int t = ws[i]; ws2[i] = run; run += t; }
        g_bsum[blockIdx.x] = run;
        __threadfence();
        atomicAdd(&g_scan_cnt, 1);
        while (atomicAdd(&g_scan_cnt, 0) < NBLK) {}
    }
    __syncthreads();

    int bs = (tid < NBLK) ? g_bsum[tid] : 0;
    int mpre = (tid < (int)blockIdx.x) ? bs : 0;
    int mtot = bs;
    #pragma unroll
    for (int off = 16; off > 0; off >>= 1) {
        mpre += __shfl_xor_sync(0xffffffffu, mpre, off);
        mtot += __shfl_xor_sync(0xffffffffu, mtot, off);
    }
    __syncthreads();
    if (lane == 0) { ws[wid] = mpre; }
    __shared__ int wt[8];
    if (lane == 0) { wt[wid] = mtot; }
    __syncthreads();
    if (tid == 0) {
        int a = 0, t = 0;
        #pragma unroll
        for (int i = 0; i < 8; i++) { a += ws[i]; t += wt[i]; }
        spre = a; stot = t;
    }
    __syncthreads();
    if (blockIdx.x == NBLK - 1 && tid == 0) g_off[N_NODES] = stot;

    if (v < N_NODES) {
        int excl = (x - d) + ws2[wid] + spre;
        g_off[v] = excl;
        g_cursor[v] = excl;
        g_dis[v] = rsqrtf((float)(d + 1));
    }
}

// ---- fill CSR (side stream; overlaps layer-1 GEMM) ----
__global__ void __launch_bounds__(256) k_fill() {
    int e = blockIdx.x * 256 + threadIdx.x;
    if (e < N_EDGES) {
        int c = g_col[e];
        int pos = atomicAdd(&g_cursor[c], 1);
        g_csr[pos] = g_row[e];
    }
}

// ---- W prep (side stream) ----
__global__ void __launch_bounds__(256) k_wprep(const float* __restrict__ W_emb,
                                               const float* __restrict__ W_layers) {
    int i = blockIdx.x * 256 + threadIdx.x;
    if (i >= 5 * 128 * 32) return;
    int w = i / (128 * 32), r = i % (128 * 32);
    const float* src = (w == 0) ? W_emb : (W_layers + (w - 1) * 16384);
    float4 a = ((const float4*)src)[r];
    u32 h0 = cvt2(a.y, a.x), h1 = cvt2(a.w, a.z);
    float l0 = a.x - bf_lo(h0), l1 = a.y - bf_hi(h0);
    float l2 = a.z - bf_lo(h1), l3 = a.w - bf_hi(h1);
    u32 q0 = cvt2(l1, l0), q1 = cvt2(l3, l2);
    int base = w * 8192 + r * 2;
    g_Whi[base] = h0; g_Whi[base + 1] = h1;
    g_Wlo[base] = q0; g_Wlo[base + 1] = q1;
}

// ---------------- persistent tensor-core GEMM (no tail wave; W staged once) ----------
// mode 0: A = x (fp32), out = g_h = bf16x2(A W^T + bias)
// mode 1: A = g_h (bf16x2), out = g_tb = bf16x2(dis[row] * (A W^T))
__global__ void __launch_bounds__(256, 2) k_mma(const void* __restrict__ A,
                                                const u32* __restrict__ Whi,
                                                const u32* __restrict__ Wlo,
                                                const float* __restrict__ bias,
                                                int mode) {
    extern __shared__ u32 smu[];
    u32* sAhi = smu;
    u32* sBhi = smu + 128 * SKW;
    u32* sBlo = smu + 2 * 128 * SKW;

    int tid = threadIdx.x;
    int lane = tid & 31, warp = tid >> 5;
    int g = lane >> 2, tig = lane & 3;
    int wr = (warp & 3) * 32;
    int wc = (warp >> 2) * 64;

    // stage W once (reused for all tiles this block processes)
    #pragma unroll
    for (int i = 0; i < 16; i++) {
        int f = tid + i * 256;
        int o = f >> 5, q = f & 31;
        uint2 vh = ((const uint2*)Whi)[f];
        uint2 vl = ((const uint2*)Wlo)[f];
        int idx = o * SKW + q * 2;
        sBhi[idx] = vh.x; sBhi[idx + 1] = vh.y;
        sBlo[idx] = vl.x; sBlo[idx + 1] = vl.y;
    }

    u32 base = smem_u32(smu);
    u32 aoff0 = (u32)((wr + (lane & 15)) * (SKW * 4) + ((lane >> 4) * 16));
    u32 aoff1 = aoff0 + 16 * (SKW * 4);
    u32 boff[4];
    #pragma unroll
    for (int np = 0; np < 4; np++) {
        int orow = wc + np * 16 + (lane & 7) + ((lane >> 4) & 1) * 8;
        boff[np] = (u32)(orow * (SKW * 4) + (((lane >> 3) & 1) * 16));
    }
    const u32 OF_BHI = 128 * SKW * 4, OF_BLO = 2 * 128 * SKW * 4;

    for (int tile = blockIdx.x; tile < MMA_TILES; tile += MMA_GRID) {
        int row0 = tile * 128;

        if (mode == 0) {
            const float4* Af = (const float4*)A;
            #pragma unroll
            for (int i = 0; i < 16; i++) {
                int f = tid + i * 256;
                int r = f >> 5, c4 = f & 31;
                int gr = row0 + r;
                float4 a = (gr < N_NODES) ? Af[gr * 32 + c4]
                                          : make_float4(0.f, 0.f, 0.f, 0.f);
                int idx = r * SKW + c4 * 2;
                sAhi[idx]     = cvt2(a.y, a.x);
                sAhi[idx + 1] = cvt2(a.w, a.z);
            }
        } else {
            const uint2* Ab = (const uint2*)A;
            #pragma unroll
            for (int i = 0; i < 16; i++) {
                int f = tid + i * 256;
                int r = f >> 5, q = f & 31;
                int gr = row0 + r;
                uint2 v = (gr < N_NODES) ? Ab[gr * 32 + q] : make_uint2(0u, 0u);
                int idx = r * SKW + q * 2;
                sAhi[idx] = v.x; sAhi[idx + 1] = v.y;
            }
        }
        __syncthreads();

        float acc[2][8][4];
        #pragma unroll
        for (int m = 0; m < 2; m++)
            #pragma unroll
            for (int n = 0; n < 8; n++)
                #pragma unroll
                for (int c = 0; c < 4; c++) acc[m][n][c] = 0.f;

        #pragma unroll
        for (int ks = 0; ks < 8; ks++) {
            u32 kb = ks * 32;
            u32 a[2][4];
            ldm4(a[0][0], a[0][1], a[0][2], a[0][3], base + aoff0 + kb);
            ldm4(a[1][0], a[1][1], a[1][2], a[1][3], base + aoff1 + kb);
            u32 bh[4][4], bl[4][4];
            #pragma unroll
            for (int np = 0; np < 4; np++) {
                ldm4(bh[np][0], bh[np][1], bh[np][2], bh[np][3], base + OF_BHI + boff[np] + kb);
                ldm4(bl[np][0], bl[np][1], bl[np][2], bl[np][3], base + OF_BLO + boff[np] + kb);
            }
            #pragma unroll
            for (int m = 0; m < 2; m++)
                #pragma unroll
                for (int np = 0; np < 4; np++) {
                    mma16816(acc[m][2*np][0], acc[m][2*np][1], acc[m][2*np][2], acc[m][2*np][3],
                             a[m][0], a[m][1], a[m][2], a[m][3], bh[np][0], bh[np][1]);
                    mma16816(acc[m][2*np+1][0], acc[m][2*np+1][1], acc[m][2*np+1][2], acc[m][2*np+1][3],
                             a[m][0], a[m][1], a[m][2], a[m][3], bh[np][2], bh[np][3]);
                    mma16816(acc[m][2*np][0], acc[m][2*np][1], acc[m][2*np][2], acc[m][2*np][3],
                             a[m][0], a[m][1], a[m][2], a[m][3], bl[np][0], bl[np][1]);
                    mma16816(acc[m][2*np+1][0], acc[m][2*np+1][1], acc[m][2*np+1][2], acc[m][2*np+1][3],
                             a[m][0], a[m][1], a[m][2], a[m][3], bl[np][2], bl[np][3]);
                }
        }

        #pragma unroll
        for (int m = 0; m < 2; m++) {
            int r0 = row0 + wr + m * 16 + g;
            int r1 = r0 + 8;
            bool ok0 = (r0 < N_NODES), ok1 = (r1 < N_NODES);
            if (mode == 0) {
                #pragma unroll
                for (int n = 0; n < 8; n++) {
                    int col = wc + n * 8 + 2 * tig;
                    float b0 = bias[col], b1 = bias[col + 1];
                    if (ok0) g_h[r0 * 64 + col / 2] = cvt2(acc[m][n][1] + b1, acc[m][n][0] + b0);
                    if (ok1) g_h[r1 * 64 + col / 2] = cvt2(acc[m][n][3] + b1, acc[m][n][2] + b0);
                }
            } else {
                float d0 = ok0 ? g_dis[r0] : 0.f;
                float d1 = ok1 ? g_dis[r1] : 0.f;
                #pragma unroll
                for (int n = 0; n < 8; n++) {
                    int col = wc + n * 8 + 2 * tig;
                    if (ok0) g_tb[r0 * 64 + col / 2] = cvt2(acc[m][n][1] * d0, acc[m][n][0] * d0);
                    if (ok1) g_tb[r1 * 64 + col / 2] = cvt2(acc[m][n][3] * d1, acc[m][n][2] * d1);
                }
            }
        }
        __syncthreads();   // A smem reuse fence for next tile
    }
}

// ------- fused CSR gather (bf16 msgs) + residual + relu + LayerNorm (+pool) -------
__global__ void __launch_bounds__(512) k_gln(const float* __restrict__ b,
                                             const float* __restrict__ gamma,
                                             const float* __restrict__ beta,
                                             const float* __restrict__ Wout) {
    __shared__ float ssum[N_GRAPHS];
    __shared__ int   scnt[N_GRAPHS];
    const bool pool = (Wout != nullptr);
    int tid = threadIdx.x;
    if (pool) {
        if (tid < N_GRAPHS) { ssum[tid] = 0.f; scnt[tid] = 0; }
        __syncthreads();
    }

    int v = (blockIdx.x * blockDim.x + tid) >> 5;
    int lane = tid & 31;
    bool active = (v < N_NODES);
    float4 o = make_float4(0.f, 0.f, 0.f, 0.f);

    if (active) {
        const uint2* T = (const uint2*)g_tb;
        uint2 sv = T[v * 32 + lane];
        float a0 = bf_lo(sv.x), a1 = bf_hi(sv.x), a2 = bf_lo(sv.y), a3 = bf_hi(sv.y);

        int i = g_off[v], e = g_off[v + 1];
        for (; i + 8 <= e; i += 8) {
            int r0 = __ldg(&g_csr[i]);
            int r1 = __ldg(&g_csr[i + 1]);
            int r2 = __ldg(&g_csr[i + 2]);
            int r3 = __ldg(&g_csr[i + 3]);
            int r4 = __ldg(&g_csr[i + 4]);
            int r5 = __ldg(&g_csr[i + 5]);
            int r6 = __ldg(&g_csr[i + 6]);
            int r7 = __ldg(&g_csr[i + 7]);
            uint2 m0 = T[r0 * 32 + lane];
            uint2 m1 = T[r1 * 32 + lane];
            uint2 m2 = T[r2 * 32 + lane];
            uint2 m3 = T[r3 * 32 + lane];
            uint2 m4 = T[r4 * 32 + lane];
            uint2 m5 = T[r5 * 32 + lane];
            uint2 m6 = T[r6 * 32 + lane];
            uint2 m7 = T[r7 * 32 + lane];
            add4(a0, a1, a2, a3, m0); add4(a0, a1, a2, a3, m1);
            add4(a0, a1, a2, a3, m2); add4(a0, a1, a2, a3, m3);
            add4(a0, a1, a2, a3, m4); add4(a0, a1, a2, a3, m5);
            add4(a0, a1, a2, a3, m6); add4(a0, a1, a2, a3, m7);
        }
        for (; i + 4 <= e; i += 4) {
            int r0 = __ldg(&g_csr[i]);
            int r1 = __ldg(&g_csr[i + 1]);
            int r2 = __ldg(&g_csr[i + 2]);
            int r3 = __ldg(&g_csr[i + 3]);
            uint2 m0 = T[r0 * 32 + lane];
            uint2 m1 = T[r1 * 32 + lane];
            uint2 m2 = T[r2 * 32 + lane];
            uint2 m3 = T[r3 * 32 + lane];
            add4(a0, a1, a2, a3, m0); add4(a0, a1, a2, a3, m1);
            add4(a0, a1, a2, a3, m2); add4(a0, a1, a2, a3, m3);
        }
        for (; i < e; i++) {
            int r = __ldg(&g_csr[i]);
            add4(a0, a1, a2, a3, T[r * 32 + lane]);
        }

        float dv = g_dis[v];
        uint2 hb = ((const uint2*)g_h)[v * 32 + lane];
        float h0 = bf_lo(hb.x), h1 = bf_hi(hb.x), h2 = bf_lo(hb.y), h3 = bf_hi(hb.y);
        float4 bv = ((const float4*)b)[lane];
        float x0 = h0 + fmaxf(dv * a0 + bv.x, 0.f);
        float x1 = h1 + fmaxf(dv * a1 + bv.y, 0.f);
        float x2 = h2 + fmaxf(dv * a2 + bv.z, 0.f);
        float x3 = h3 + fmaxf(dv * a3 + bv.w, 0.f);

        float s = x0 + x1 + x2 + x3;
        #pragma unroll
        for (int off = 16; off > 0; off >>= 1) s += __shfl_xor_sync(0xffffffffu, s, off);
        float mu = s * (1.f / 128.f);
        float d0 = x0 - mu, d1 = x1 - mu, d2 = x2 - mu, d3 = x3 - mu;
        float q = d0 * d0 + d1 * d1 + d2 * d2 + d3 * d3;
        #pragma unroll
        for (int off = 16; off > 0; off >>= 1) q += __shfl_xor_sync(0xffffffffu, q, off);
        float rs = rsqrtf(q * (1.f / 128.f) + LN_EPS);
        float4 gv = ((const float4*)gamma)[lane];
        float4 be = ((const float4*)beta)[lane];
        o.x = d0 * rs * gv.x + be.x;
        o.y = d1 * rs * gv.y + be.y;
        o.z = d2 * rs * gv.z + be.z;
        o.w = d3 * rs * gv.w + be.w;
        uint2 ho;
        ho.x = cvt2(o.y, o.x);
        ho.y = cvt2(o.w, o.z);
        ((uint2*)g_h)[v * 32 + lane] = ho;
    }

    if (pool) {
        float s = 0.f;
        if (active) {
            float4 wv = ((const float4*)Wout)[lane];
            s = o.x * wv.x + o.y * wv.y + o.z * wv.z + o.w * wv.w;
        }
        #pragma unroll
        for (int off = 16; off > 0; off >>= 1) s += __shfl_xor_sync(0xffffffffu, s, off);
        if (active && lane == 0) {
            int bg = g_batch[v];
            atomicAdd(&ssum[bg], s);
            atomicAdd(&scnt[bg], 1);
        }
        __syncthreads();
        if (tid < N_GRAPHS && scnt[tid] > 0) {
            atomicAdd(&g_sums[tid], ssum[tid]);
            atomicAdd(&g_cnts[tid], scnt[tid]);
        }
    }
}

// ---- output + state re-zero (edeg, pool accumulators, scan counter) ----
__global__ void __launch_bounds__(256) k_out(float* out) {
    int i = blockIdx.x * 256 + threadIdx.x;
    if (blockIdx.x == 0 && threadIdx.x < N_GRAPHS) {
        int g = threadIdx.x;
        out[g] = g_sums[g] / fmaxf((float)g_cnts[g], 1.f);
        g_sums[g] = 0.f;
        g_cnts[g] = 0;
    }
    if (blockIdx.x == 0 && threadIdx.x == 32) g_scan_cnt = 0;
    if (i < N_NODES) g_edeg[i] = 0;
}

// ---------------- launch ----------------
extern "C" void kernel_launch(void* const* d_in, const int* in_sizes, int n_in,
                              void* d_out, int out_size) {
    const float* x        = (const float*)d_in[0];
    const void*  ei       = d_in[1];
    const void*  batch    = d_in[2];
    const float* W_emb    = (const float*)d_in[3];
    const float* b_emb    = (const float*)d_in[4];
    const float* W_layers = (const float*)d_in[5];
    const float* b_layers = (const float*)d_in[6];
    const float* ln_gamma = (const float*)d_in[7];
    const float* ln_beta  = (const float*)d_in[8];
    const float* W_out    = (const float*)d_in[9];
    float* out = (float*)d_out;

    const int MMA_SMEM = 3 * 128 * SKW * sizeof(u32);   // 104,448 B -> 2 CTAs/SM
    static cudaStream_t s2 = nullptr;
    static cudaEvent_t evA = nullptr, evB = nullptr, evC = nullptr, evD = nullptr;
    if (!s2) {
        cudaFuncSetAttribute(k_mma, cudaFuncAttributeMaxDynamicSharedMemorySize, MMA_SMEM);
        cudaStreamCreateWithFlags(&s2, cudaStreamNonBlocking);
        cudaEventCreateWithFlags(&evA, cudaEventDisableTiming);
        cudaEventCreateWithFlags(&evB, cudaEventDisableTiming);
        cudaEventCreateWithFlags(&evC, cudaEventDisableTiming);
        cudaEventCreateWithFlags(&evD, cudaEventDisableTiming);
    }

    u32* d_h = nullptr;
    cudaGetSymbolAddress((void**)&d_h, g_h);
    u32* whi = nullptr;
    cudaGetSymbolAddress((void**)&whi, g_Whi);
    u32* wlo = nullptr;
    cudaGetSymbolAddress((void**)&wlo, g_Wlo);

    // fork: side stream does W prep + embedding GEMM + row/batch convert
    cudaEventRecord(evA, 0);
    cudaStreamWaitEvent(s2, evA, 0);
    k_wprep<<<WPBLK, 256, 0, s2>>>(W_emb, W_layers);
    k_mma<<<MMA_GRID, 256, MMA_SMEM, s2>>>(x, whi, wlo, b_emb, 0);
    cudaEventRecord(evB, s2);
    k_aux<<<EBLK2, 256, 0, s2>>>(ei, batch);

    // main stream: critical-path preamble (col+deg -> fused scan)
    k_deg<<<EBLK2, 256>>>(ei);
    k_scan<<<NBLK, 256>>>();
    cudaEventRecord(evC, 0);

    // side stream: CSR fill (needs aux rows + scan cursors), overlaps layer-1 GEMM
    cudaStreamWaitEvent(s2, evC, 0);
    k_fill<<<EBLK2 * 2, 256, 0, s2>>>();
    cudaEventRecord(evD, s2);

    cudaStreamWaitEvent(0, evB, 0);       // embedding result ready

    int gln_blocks = (N_NODES + 15) / 16;    // 3125
    for (int i = 0; i < 4; i++) {
        k_mma<<<MMA_GRID, 256, MMA_SMEM>>>(d_h, whi + (1 + i) * 8192, wlo + (1 + i) * 8192,
                                           nullptr, 1);
        if (i == 0) cudaStreamWaitEvent(0, evD, 0);   // CSR ready before first gather
        k_gln<<<gln_blocks, 512>>>(b_layers + i * HID, ln_gamma + i * HID, ln_beta + i * HID,
                                   (i == 3) ? W_out : nullptr);
    }

    k_out<<<NBLK, 256>>>(out);
}